// round 1
// baseline (speedup 1.0000x reference)
#include <cuda_runtime.h>

#define B_DIM 128
#define N_DIM 8192
#define HW    49

__device__ __forceinline__ float ex2(float x) {
    float y;
    asm("ex2.approx.ftz.f32 %0, %1;" : "=f"(y) : "f"(x));
    return y;
}

__global__ __launch_bounds__(128, 16) void rsca_kernel(
    const float* __restrict__ x, const float* __restrict__ y,
    const float* __restrict__ swq, const float* __restrict__ swk,
    const float* __restrict__ swv, const float* __restrict__ sbq,
    const float* __restrict__ sbk, const float* __restrict__ sbv,
    const float* __restrict__ swo, const float* __restrict__ sbo,
    float* __restrict__ out)
{
    const int n = blockIdx.x;     // column index 0..8191
    const int i = threadIdx.x;    // b index 0..127

    const float wq = *swq, wk = *swk, wv = *swv;
    const float bq = *sbq, bk = *sbk, bv = *sbv;
    const float wo = *swo, bo = *sbo;

    // ---- Pooling: thread i averages x[i][n][0..48] (49 contiguous floats) ----
    const float* xr = x + ((size_t)i * N_DIM + (size_t)n) * HW;
    float s0 = 0.f, s1 = 0.f, s2 = 0.f, s3 = 0.f;
    #pragma unroll
    for (int t = 0; t < 48; t += 4) {
        s0 += xr[t + 0];
        s1 += xr[t + 1];
        s2 += xr[t + 2];
        s3 += xr[t + 3];
    }
    s0 += xr[48];
    const float ax = (s0 + s1 + s2 + s3) * (1.0f / 49.0f);   // xp[i][n]
    const float ay = y[(size_t)i * N_DIM + (size_t)n];        // y[i][n]

    // ---- q/k/v projections (k pre-scaled by log2(e)) ----
    const float L2E = 1.4426950408889634f;
    const float qx = fmaf(ax, wq, bq);
    const float qy = fmaf(ay, wq, bq);
    const float kx = fmaf(ax, wk, bk) * L2E;
    const float ky = fmaf(ay, wk, bk) * L2E;
    const float vx = fmaf(ax, wv, bv);
    const float vy = fmaf(ay, wv, bv);

    __shared__ float2 kvx[B_DIM];   // {k_log2e, v} from xp source
    __shared__ float2 kvy[B_DIM];   // {k_log2e, v} from y  source
    __shared__ float4 wred[4];      // per-warp {kxmax, kxmin, kymax, kymin}

    kvx[i] = make_float2(kx, vx);
    kvy[i] = make_float2(ky, vy);

    // ---- Block reduce max/min of kx, ky (for analytic per-row softmax max) ----
    float kxmx = kx, kxmn = kx, kymx = ky, kymn = ky;
    #pragma unroll
    for (int off = 16; off; off >>= 1) {
        kxmx = fmaxf(kxmx, __shfl_xor_sync(0xFFFFFFFFu, kxmx, off));
        kxmn = fminf(kxmn, __shfl_xor_sync(0xFFFFFFFFu, kxmn, off));
        kymx = fmaxf(kymx, __shfl_xor_sync(0xFFFFFFFFu, kymx, off));
        kymn = fminf(kymn, __shfl_xor_sync(0xFFFFFFFFu, kymn, off));
    }
    if ((i & 31) == 0) wred[i >> 5] = make_float4(kxmx, kxmn, kymx, kymn);
    __syncthreads();

    {
        float4 r0 = wred[0], r1 = wred[1], r2 = wred[2], r3 = wred[3];
        kxmx = fmaxf(fmaxf(r0.x, r1.x), fmaxf(r2.x, r3.x));
        kxmn = fminf(fminf(r0.y, r1.y), fminf(r2.y, r3.y));
        kymx = fmaxf(fmaxf(r0.z, r1.z), fmaxf(r2.z, r3.z));
        kymn = fminf(fminf(r0.w, r1.w), fminf(r2.w, r3.w));
    }

    // max_j(q * k_j) = q*kmax (q>=0) else q*kmin  (k already log2e-scaled)
    const float nm1 = -((qx >= 0.f) ? qx * kxmx : qx * kxmn);  // self_x : qx,kvx
    const float nm2 = -((qy >= 0.f) ? qy * kymx : qy * kymn);  // self_y : qy,kvy
    const float nm3 = -((qx >= 0.f) ? qx * kymx : qx * kymn);  // cross_x: qx,kvy
    const float nm4 = -((qy >= 0.f) ? qy * kxmx : qy * kxmn);  // cross_y: qy,kvx

    // ---- Fused 4-combo attention row (MUFU-bound inner loop) ----
    float n1 = 0.f, d1 = 0.f, n2 = 0.f, d2 = 0.f;
    float n3 = 0.f, d3 = 0.f, n4 = 0.f, d4 = 0.f;

    #pragma unroll 4
    for (int j = 0; j < B_DIM; ++j) {
        const float2 px = kvx[j];
        const float2 py = kvy[j];
        const float e1 = ex2(fmaf(qx, px.x, nm1));
        const float e2 = ex2(fmaf(qy, py.x, nm2));
        const float e3 = ex2(fmaf(qx, py.x, nm3));
        const float e4 = ex2(fmaf(qy, px.x, nm4));
        d1 += e1; n1 = fmaf(e1, px.y, n1);
        d2 += e2; n2 = fmaf(e2, py.y, n2);
        d3 += e3; n3 = fmaf(e3, py.y, n3);
        d4 += e4; n4 = fmaf(e4, px.y, n4);
    }

    const float osx = __fdividef(n1, d1);
    const float osy = __fdividef(n2, d2);
    const float ocx = __fdividef(n3, d3);
    const float ocy = __fdividef(n4, d4);

    // c_f_x = xp + wo*(self + cross) + 2*bo  (likewise for y)
    const float ox = fmaf(wo, osx + ocx, ax + 2.0f * bo);
    const float oy = fmaf(wo, osy + ocy, ay + 2.0f * bo);

    out[(size_t)i * (2 * N_DIM) + (size_t)n]         = ox;
    out[(size_t)i * (2 * N_DIM) + N_DIM + (size_t)n] = oy;
}

extern "C" void kernel_launch(void* const* d_in, const int* in_sizes, int n_in,
                              void* d_out, int out_size) {
    const float* x   = (const float*)d_in[0];
    const float* y   = (const float*)d_in[1];
    const float* swq = (const float*)d_in[2];
    const float* swk = (const float*)d_in[3];
    const float* swv = (const float*)d_in[4];
    const float* sbq = (const float*)d_in[5];
    const float* sbk = (const float*)d_in[6];
    const float* sbv = (const float*)d_in[7];
    const float* swo = (const float*)d_in[8];
    const float* sbo = (const float*)d_in[9];
    float* out = (float*)d_out;

    rsca_kernel<<<N_DIM, B_DIM>>>(x, y, swq, swk, swv, sbq, sbk, sbv, swo, sbo, out);
}

// round 2
// speedup vs baseline: 2.1339x; 2.1339x over previous
#include <cuda_runtime.h>

#define B_DIM 128
#define N_DIM 8192
#define HW    49

__device__ __forceinline__ float ex2(float x) {
    float y;
    asm("ex2.approx.ftz.f32 %0, %1;" : "=f"(y) : "f"(x));
    return y;
}

__global__ __launch_bounds__(128, 12) void rsca_kernel(
    const float* __restrict__ x, const float* __restrict__ y,
    const float* __restrict__ swq, const float* __restrict__ swk,
    const float* __restrict__ swv, const float* __restrict__ sbq,
    const float* __restrict__ sbk, const float* __restrict__ sbv,
    const float* __restrict__ swo, const float* __restrict__ sbo,
    float* __restrict__ out)
{
    const int n = blockIdx.x;     // column index 0..8191
    const int i = threadIdx.x;    // b index 0..127

    const float wq = *swq, wk = *swk, wv = *swv;
    const float bq = *sbq, bk = *sbk, bv = *sbv;
    const float wo = *swo, bo = *sbo;

    // ---- Pooling via aligned float4 loads ----
    // Element offset s = (i*8192+n)*49; s mod 4 == n mod 4 == a (uniform per block).
    // base = &x[s-a] is 16B-aligned. Window w[p]=base[p]; valid row = p in [a, a+48].
    const int a = n & 3;
    const float* base = x + ((size_t)i * N_DIM + (size_t)n) * HW - a;
    const float4* b4 = (const float4*)base;

    float4 a0 = b4[0], a1 = b4[1], a2 = b4[2],  a3 = b4[3];
    float4 a4 = b4[4], a5 = b4[5], a6 = b4[6],  a7 = b4[7];
    float4 a8 = b4[8], a9 = b4[9], a10 = b4[10], a11 = b4[11];

    float4 t0, t1, t2;
    t0.x = a0.x + a1.x; t0.y = a0.y + a1.y; t0.z = a0.z + a1.z; t0.w = a0.w + a1.w;
    t1.x = a2.x + a3.x; t1.y = a2.y + a3.y; t1.z = a2.z + a3.z; t1.w = a2.w + a3.w;
    t2.x = a4.x + a5.x; t2.y = a4.y + a5.y; t2.z = a4.z + a5.z; t2.w = a4.w + a5.w;
    t0.x += a6.x;  t0.y += a6.y;  t0.z += a6.z;  t0.w += a6.w;
    t1.x += a7.x;  t1.y += a7.y;  t1.z += a7.z;  t1.w += a7.w;
    t2.x += a8.x;  t2.y += a8.y;  t2.z += a8.z;  t2.w += a8.w;
    t0.x += a9.x;  t0.y += a9.y;  t0.z += a9.z;  t0.w += a9.w;
    t1.x += a10.x; t1.y += a10.y; t1.z += a10.z; t1.w += a10.w;
    t2.x += a11.x; t2.y += a11.y; t2.z += a11.z; t2.w += a11.w;

    float sum = (t0.x + t0.y) + (t0.z + t0.w)
              + (t1.x + t1.y) + (t1.z + t1.w)
              + (t2.x + t2.y) + (t2.z + t2.w);

    // Subtract invalid head w[0..a), add tail w[48..48+a] (uniform branch per block)
    if (a > 0) sum -= base[0];
    if (a > 1) sum -= base[1];
    if (a > 2) sum -= base[2];
    sum += base[48];
    if (a > 0) sum += base[49];
    if (a > 1) sum += base[50];
    if (a > 2) sum += base[51];

    const float ax = sum * (1.0f / 49.0f);                    // xp[i][n]
    const float ay = y[(size_t)i * N_DIM + (size_t)n];        // y[i][n]

    // ---- q/k/v projections (k pre-scaled by log2(e)) ----
    const float L2E = 1.4426950408889634f;
    const float qx = fmaf(ax, wq, bq);
    const float qy = fmaf(ay, wq, bq);
    const float kx = fmaf(ax, wk, bk) * L2E;
    const float ky = fmaf(ay, wk, bk) * L2E;
    const float vx = fmaf(ax, wv, bv);
    const float vy = fmaf(ay, wv, bv);

    __shared__ float4 kv[B_DIM];    // {kx, vx, ky, vy}
    __shared__ float4 wred[4];      // per-warp {kxmax, kxmin, kymax, kymin}

    kv[i] = make_float4(kx, vx, ky, vy);

    // ---- Block reduce max/min of kx, ky (analytic per-row softmax max) ----
    float kxmx = kx, kxmn = kx, kymx = ky, kymn = ky;
    #pragma unroll
    for (int off = 16; off; off >>= 1) {
        kxmx = fmaxf(kxmx, __shfl_xor_sync(0xFFFFFFFFu, kxmx, off));
        kxmn = fminf(kxmn, __shfl_xor_sync(0xFFFFFFFFu, kxmn, off));
        kymx = fmaxf(kymx, __shfl_xor_sync(0xFFFFFFFFu, kymx, off));
        kymn = fminf(kymn, __shfl_xor_sync(0xFFFFFFFFu, kymn, off));
    }
    if ((i & 31) == 0) wred[i >> 5] = make_float4(kxmx, kxmn, kymx, kymn);
    __syncthreads();

    {
        float4 r0 = wred[0], r1 = wred[1], r2 = wred[2], r3 = wred[3];
        kxmx = fmaxf(fmaxf(r0.x, r1.x), fmaxf(r2.x, r3.x));
        kxmn = fminf(fminf(r0.y, r1.y), fminf(r2.y, r3.y));
        kymx = fmaxf(fmaxf(r0.z, r1.z), fmaxf(r2.z, r3.z));
        kymn = fminf(fminf(r0.w, r1.w), fminf(r2.w, r3.w));
    }

    // max_j(q * k_j) = q*kmax (q>=0) else q*kmin  (k already log2e-scaled)
    const float nm1 = -((qx >= 0.f) ? qx * kxmx : qx * kxmn);  // self_x : qx,kx
    const float nm2 = -((qy >= 0.f) ? qy * kymx : qy * kymn);  // self_y : qy,ky
    const float nm3 = -((qx >= 0.f) ? qx * kymx : qx * kymn);  // cross_x: qx,ky
    const float nm4 = -((qy >= 0.f) ? qy * kxmx : qy * kxmn);  // cross_y: qy,kx

    // ---- Fused 4-combo attention row (MUFU-bound inner loop) ----
    float n1 = 0.f, d1 = 0.f, n2 = 0.f, d2 = 0.f;
    float n3 = 0.f, d3 = 0.f, n4 = 0.f, d4 = 0.f;

    #pragma unroll 8
    for (int j = 0; j < B_DIM; ++j) {
        const float4 p = kv[j];       // {kx_j, vx_j, ky_j, vy_j}
        const float e1 = ex2(fmaf(qx, p.x, nm1));
        const float e2 = ex2(fmaf(qy, p.z, nm2));
        const float e3 = ex2(fmaf(qx, p.z, nm3));
        const float e4 = ex2(fmaf(qy, p.x, nm4));
        d1 += e1; n1 = fmaf(e1, p.y, n1);
        d2 += e2; n2 = fmaf(e2, p.w, n2);
        d3 += e3; n3 = fmaf(e3, p.w, n3);
        d4 += e4; n4 = fmaf(e4, p.y, n4);
    }

    const float osx = __fdividef(n1, d1);
    const float osy = __fdividef(n2, d2);
    const float ocx = __fdividef(n3, d3);
    const float ocy = __fdividef(n4, d4);

    // c_f_x = xp + wo*(self + cross) + 2*bo  (likewise for y)
    const float ox = fmaf(wo, osx + ocx, ax + 2.0f * bo);
    const float oy = fmaf(wo, osy + ocy, ay + 2.0f * bo);

    out[(size_t)i * (2 * N_DIM) + (size_t)n]         = ox;
    out[(size_t)i * (2 * N_DIM) + N_DIM + (size_t)n] = oy;
}

extern "C" void kernel_launch(void* const* d_in, const int* in_sizes, int n_in,
                              void* d_out, int out_size) {
    const float* x   = (const float*)d_in[0];
    const float* y   = (const float*)d_in[1];
    const float* swq = (const float*)d_in[2];
    const float* swk = (const float*)d_in[3];
    const float* swv = (const float*)d_in[4];
    const float* sbq = (const float*)d_in[5];
    const float* sbk = (const float*)d_in[6];
    const float* sbv = (const float*)d_in[7];
    const float* swo = (const float*)d_in[8];
    const float* sbo = (const float*)d_in[9];
    float* out = (float*)d_out;

    rsca_kernel<<<N_DIM, B_DIM>>>(x, y, swq, swk, swv, sbq, sbk, sbv, swo, sbo, out);
}